// round 15
// baseline (speedup 1.0000x reference)
#include <cuda_runtime.h>
#include <cuda_bf16.h>
#include <math.h>
#include <stdint.h>

#define BB 2
#define SS 2048
#define HIDD 2048
#define NHH 8
#define NKVV 1
#define HDD 256

typedef __nv_bfloat16 bf16;

// ---------------- scratch (device globals; no allocation allowed) -----------
__device__ float g_qkvf[(size_t)BB * SS * 2560];
__device__ float g_scores[(size_t)BB * NHH * SS * SS];

__device__ bf16 g_hhi[(size_t)BB * SS * HIDD];
__device__ bf16 g_hlo[(size_t)BB * SS * HIDD];
__device__ bf16 g_wT_hi[(size_t)2560 * HIDD];
__device__ bf16 g_wT_lo[(size_t)2560 * HIDD];
__device__ bf16 g_woT_hi[(size_t)HIDD * NHH * HDD];
__device__ bf16 g_woT_lo[(size_t)HIDD * NHH * HDD];
__device__ bf16 g_qhi[(size_t)BB * SS * NHH * HDD];
__device__ bf16 g_qlo[(size_t)BB * SS * NHH * HDD];
__device__ bf16 g_khi[(size_t)BB * SS * HDD];
__device__ bf16 g_klo[(size_t)BB * SS * HDD];
__device__ bf16 g_vthi[(size_t)BB * HDD * SS];
__device__ bf16 g_vtlo[(size_t)BB * HDD * SS];
__device__ bf16 g_ahi[(size_t)BB * NHH * SS * SS];
__device__ bf16 g_alo[(size_t)BB * NHH * SS * SS];
__device__ bf16 g_chi[(size_t)BB * SS * NHH * HDD];
__device__ bf16 g_clo[(size_t)BB * SS * NHH * HDD];

// ---------------- PTX helpers -------------------------------------------------
__device__ __forceinline__ uint32_t smem_to_u32(const void* p) {
    uint32_t a;
    asm("{ .reg .u64 t; cvta.to.shared.u64 t, %1; cvt.u32.u64 %0, t; }"
        : "=r"(a) : "l"(p));
    return a;
}
#define CPA(dst, src) \
    asm volatile("cp.async.cg.shared.global [%0], [%1], 16;" :: "r"(dst), "l"(src))
#define CPC() asm volatile("cp.async.commit_group;" ::: "memory")
#define CPW(n) asm volatile("cp.async.wait_group %0;" :: "n"(n) : "memory")
#define LDSM4(r, addr) \
    asm volatile("ldmatrix.sync.aligned.m8n8.x4.shared.b16 {%0,%1,%2,%3}, [%4];" \
        : "=r"((r)[0]), "=r"((r)[1]), "=r"((r)[2]), "=r"((r)[3]) : "r"(addr))

__device__ __forceinline__ void mma16816(float* c, const uint32_t* a, const uint32_t* b) {
    asm volatile(
        "mma.sync.aligned.m16n8k16.row.col.f32.bf16.bf16.f32 "
        "{%0,%1,%2,%3}, {%4,%5,%6,%7}, {%8,%9}, {%0,%1,%2,%3};"
        : "+f"(c[0]), "+f"(c[1]), "+f"(c[2]), "+f"(c[3])
        : "r"(a[0]), "r"(a[1]), "r"(a[2]), "r"(a[3]), "r"(b[0]), "r"(b[1]));
}

__device__ __forceinline__ void splitf(float x, bf16& hi, bf16& lo) {
    hi = __float2bfloat16(x);
    lo = __float2bfloat16(x - __bfloat162float(hi));
}
__device__ __forceinline__ uint32_t pack2(bf16 a, bf16 b) {
    return (uint32_t)__bfloat16_as_ushort(a) | ((uint32_t)__bfloat16_as_ushort(b) << 16);
}

// ---------------- staging (512 threads, BN=256) --------------------------------
__device__ __forceinline__ void stage_tiles_512(
    uint32_t stg, const bf16* Ah, const bf16* Al,
    const bf16* Bh, const bf16* Bl, int lda, int ldb, int tid)
{
    constexpr uint32_t ATB = 16384;
    constexpr uint32_t BTB = 256 * 128;
#pragma unroll
    for (int it = 0; it < 2; ++it) {
        int id = tid + it * 512;
        int row = id >> 3, cc = id & 7;
        uint32_t soff = (uint32_t)(row * 128 + ((cc ^ (row & 7)) << 4));
        size_t go = (size_t)row * lda + cc * 8;
        CPA(stg + soff,       Ah + go);
        CPA(stg + ATB + soff, Al + go);
    }
#pragma unroll
    for (int it = 0; it < 4; ++it) {
        int id = tid + it * 512;
        int row = id >> 3, cc = id & 7;
        uint32_t soff = (uint32_t)(row * 128 + ((cc ^ (row & 7)) << 4));
        size_t go = (size_t)row * ldb + cc * 8;
        CPA(stg + 2 * ATB + soff,       Bh + go);
        CPA(stg + 2 * ATB + BTB + soff, Bl + go);
    }
}

// ---------------- BN=256 GEMM, 512 threads (16 warps, warp tile 32x64) ----------
// causal: 0 dense; 1 QK tile-skip; 2 AV bounded-k. Heavy-first when causal.
// Cf: optional fp32 out; Chi/Clo: optional bf16 hi/lo out.
__global__ __launch_bounds__(512) void gemm_bf16_512(
    const bf16* __restrict__ Ahi, const bf16* __restrict__ Alo,
    const bf16* __restrict__ Bhi, const bf16* __restrict__ Blo,
    float* __restrict__ Cf, bf16* __restrict__ Chi, bf16* __restrict__ Clo,
    int K, int lda, int ldb, int ldc,
    long long sAb, long long sAh, long long sBb, long long sBh,
    long long sCb, long long sCh, int nh, int causal)
{
    constexpr uint32_t ATB = 16384;
    constexpr uint32_t BTB = 256 * 128;
    constexpr uint32_t STG = 2 * ATB + 2 * BTB;

    extern __shared__ char dsm[];
    const uint32_t sb = smem_to_u32(dsm);

    int by = blockIdx.y;
    if (causal) by = gridDim.y - 1 - by;
    const int bm = by * 128;
    const int bn = blockIdx.x * 256;
    if (causal == 1 && bn >= bm + 128) return;

    const int z = blockIdx.z;
    const int b = z / nh, h = z % nh;
    const size_t aoff = (size_t)b * sAb + (size_t)h * sAh;
    const size_t boff = (size_t)b * sBb + (size_t)h * sBh;
    const size_t coff = (size_t)b * sCb + (size_t)h * sCh;

    const int tid  = threadIdx.x;
    const int lane = tid & 31;
    const int wid  = tid >> 5;           // 0..15
    const int g = lane >> 2, t = lane & 3;
    const int m0 = (wid & 3) * 32;       // 4 warp-rows
    const int n0 = (wid >> 2) * 64;      // 4 warp-cols

    const bf16* Ah0 = Ahi + aoff + (size_t)bm * lda;
    const bf16* Al0 = Alo + aoff + (size_t)bm * lda;
    const bf16* Bh0 = Bhi + boff + (size_t)bn * ldb;
    const bf16* Bl0 = Blo + boff + (size_t)bn * ldb;

    float acc[2][8][4];
#pragma unroll
    for (int i = 0; i < 2; i++)
#pragma unroll
        for (int j = 0; j < 8; j++)
#pragma unroll
            for (int r = 0; r < 4; r++) acc[i][j][r] = 0.f;

    int nchunks = K / 64;
    if (causal == 2) {
        int nc = (bm + 128) / 64;        // attn rows zero beyond bm+128
        if (nc < nchunks) nchunks = nc;
    }

    const int arow = m0 + (lane & 15);
    const int akh  = lane >> 4;
    const int brow = n0 + ((lane >> 3) & 1) * 8 + (lane & 7);
    const int bkh  = lane >> 4;

#pragma unroll
    for (int s = 0; s < 2; ++s) {
        if (s < nchunks)
            stage_tiles_512(sb + (uint32_t)s * STG, Ah0 + s * 64, Al0 + s * 64,
                            Bh0 + s * 64, Bl0 + s * 64, lda, ldb, tid);
        CPC();
    }

    for (int c = 0; c < nchunks; ++c) {
        if (c + 1 < nchunks) CPW(1); else CPW(0);
        __syncthreads();

        const uint32_t stg = sb + (uint32_t)(c & 1) * STG;
        const uint32_t aHi = stg, aLo = stg + ATB;
        const uint32_t bHi = stg + 2 * ATB, bLo = stg + 2 * ATB + BTB;

#pragma unroll
        for (int ks = 0; ks < 4; ++ks) {
            uint32_t af[2][4], bfr[8][2];

            // pass 1: ah x bhi
#pragma unroll
            for (int mt = 0; mt < 2; ++mt) {
                int row = arow + mt * 16;
                uint32_t off = (uint32_t)(row * 128 +
                    (((2 * ks + akh) ^ (row & 7)) << 4));
                LDSM4(af[mt], aHi + off);
            }
#pragma unroll
            for (int p = 0; p < 4; ++p) {
                int row = brow + p * 16;
                uint32_t off = (uint32_t)(row * 128 +
                    (((2 * ks + bkh) ^ (row & 7)) << 4));
                uint32_t rh[4];
                LDSM4(rh, bHi + off);
                bfr[2 * p][0] = rh[0]; bfr[2 * p][1] = rh[2];
                bfr[2 * p + 1][0] = rh[1]; bfr[2 * p + 1][1] = rh[3];
            }
#pragma unroll
            for (int mt = 0; mt < 2; ++mt)
#pragma unroll
                for (int nt = 0; nt < 8; ++nt)
                    mma16816(acc[mt][nt], af[mt], bfr[nt]);

            // pass 2: al x bhi (reload a only; bh stays live)
#pragma unroll
            for (int mt = 0; mt < 2; ++mt) {
                int row = arow + mt * 16;
                uint32_t off = (uint32_t)(row * 128 +
                    (((2 * ks + akh) ^ (row & 7)) << 4));
                LDSM4(af[mt], aLo + off);
            }
#pragma unroll
            for (int mt = 0; mt < 2; ++mt)
#pragma unroll
                for (int nt = 0; nt < 8; ++nt)
                    mma16816(acc[mt][nt], af[mt], bfr[nt]);

            // pass 3: ah x blo (reload a and b)
#pragma unroll
            for (int mt = 0; mt < 2; ++mt) {
                int row = arow + mt * 16;
                uint32_t off = (uint32_t)(row * 128 +
                    (((2 * ks + akh) ^ (row & 7)) << 4));
                LDSM4(af[mt], aHi + off);
            }
#pragma unroll
            for (int p = 0; p < 4; ++p) {
                int row = brow + p * 16;
                uint32_t off = (uint32_t)(row * 128 +
                    (((2 * ks + bkh) ^ (row & 7)) << 4));
                uint32_t rl[4];
                LDSM4(rl, bLo + off);
                bfr[2 * p][0] = rl[0]; bfr[2 * p][1] = rl[2];
                bfr[2 * p + 1][0] = rl[1]; bfr[2 * p + 1][1] = rl[3];
            }
#pragma unroll
            for (int mt = 0; mt < 2; ++mt)
#pragma unroll
                for (int nt = 0; nt < 8; ++nt)
                    mma16816(acc[mt][nt], af[mt], bfr[nt]);
        }

        __syncthreads();
        int pf = c + 2;
        if (pf < nchunks) {
            stage_tiles_512(sb + (uint32_t)(pf & 1) * STG,
                            Ah0 + pf * 64, Al0 + pf * 64,
                            Bh0 + pf * 64, Bl0 + pf * 64, lda, ldb, tid);
            CPC();
        }
    }

#pragma unroll
    for (int mt = 0; mt < 2; ++mt) {
#pragma unroll
        for (int nt = 0; nt < 8; ++nt) {
            int row = bm + m0 + mt * 16 + g;
            int col = bn + n0 + nt * 8 + 2 * t;
            if (Cf) {
                *reinterpret_cast<float2*>(Cf + coff + (size_t)row * ldc + col) =
                    make_float2(acc[mt][nt][0], acc[mt][nt][1]);
                *reinterpret_cast<float2*>(Cf + coff + (size_t)(row + 8) * ldc + col) =
                    make_float2(acc[mt][nt][2], acc[mt][nt][3]);
            }
            if (Chi) {
                bf16 h0, l0, h1, l1;
                splitf(acc[mt][nt][0], h0, l0);
                splitf(acc[mt][nt][1], h1, l1);
                *reinterpret_cast<uint32_t*>(Chi + coff + (size_t)row * ldc + col) = pack2(h0, h1);
                *reinterpret_cast<uint32_t*>(Clo + coff + (size_t)row * ldc + col) = pack2(l0, l1);
                splitf(acc[mt][nt][2], h0, l0);
                splitf(acc[mt][nt][3], h1, l1);
                *reinterpret_cast<uint32_t*>(Chi + coff + (size_t)(row + 8) * ldc + col) = pack2(h0, h1);
                *reinterpret_cast<uint32_t*>(Clo + coff + (size_t)(row + 8) * ldc + col) = pack2(l0, l1);
            }
        }
    }
}

// ---------------- elementwise bodies (proven) ----------------------------------
__device__ __forceinline__ void convert_body(
    const float* __restrict__ in, bf16* __restrict__ hi, bf16* __restrict__ lo,
    int idx, int n4)
{
    if (idx >= n4) return;
    float4 f = reinterpret_cast<const float4*>(in)[idx];
    bf16 h0,l0,h1,l1,h2,l2,h3,l3;
    splitf(f.x,h0,l0); splitf(f.y,h1,l1); splitf(f.z,h2,l2); splitf(f.w,h3,l3);
    reinterpret_cast<uint2*>(hi)[idx] = make_uint2(pack2(h0,h1), pack2(h2,h3));
    reinterpret_cast<uint2*>(lo)[idx] = make_uint2(pack2(l0,l1), pack2(l2,l3));
}

__device__ __forceinline__ void tr_body(
    float (*tile)[33],
    const float* __restrict__ in, bf16* __restrict__ ohi, bf16* __restrict__ olo,
    int R, int Cstride, int bx, int by, int tid)
{
    int c0 = bx * 32, r0 = by * 32;
    {
        int lr  = tid >> 3;
        int lc4 = (tid & 7) * 4;
        float4 f = *reinterpret_cast<const float4*>(
            in + (size_t)(r0 + lr) * Cstride + c0 + lc4);
        tile[lr][lc4 + 0] = f.x;
        tile[lr][lc4 + 1] = f.y;
        tile[lr][lc4 + 2] = f.z;
        tile[lr][lc4 + 3] = f.w;
    }
    __syncthreads();
    {
        int c  = tid >> 3;
        int rg = (tid & 7) * 4;
        bf16 h[4], l[4];
#pragma unroll
        for (int j = 0; j < 4; ++j)
            splitf(tile[rg + j][c], h[j], l[j]);
        size_t o = (size_t)(c0 + c) * R + r0 + rg;
        *reinterpret_cast<uint2*>(ohi + o) = make_uint2(pack2(h[0],h[1]), pack2(h[2],h[3]));
        *reinterpret_cast<uint2*>(olo + o) = make_uint2(pack2(l[0],l[1]), pack2(l[2],l[3]));
    }
}

__device__ __forceinline__ void rope_body(
    const float* __restrict__ x, const int* __restrict__ pos_ids,
    bf16* __restrict__ xhi, bf16* __restrict__ xlo,
    int nheads, int in_stride, int idx)
{
    const int half = HDD / 2;
    int total = BB * SS * nheads * half;
    if (idx >= total) return;
    int d = idx % half;
    int tt = idx / half;
    int h = tt % nheads;
    int s = (tt / nheads) % SS;
    int b = tt / (nheads * SS);

    float pos = (float)pos_ids[b * SS + s];
    float inv = exp2f(-(float)d * 0.103810253f);
    float ang = pos * inv;
    float c = cosf(ang), sn = sinf(ang);

    size_t ibase = (size_t)(b * SS + s) * in_stride + h * HDD;
    float x1 = x[ibase + d];
    float x2 = x[ibase + d + half];
    float r1 = x1 * c - x2 * sn;
    float r2 = x2 * c + x1 * sn;
    bf16 h1, l1, h2, l2;
    splitf(r1, h1, l1);
    splitf(r2, h2, l2);
    size_t obase = ((size_t)(b * SS + s) * nheads + h) * HDD;
    xhi[obase + d] = h1;        xlo[obase + d] = l1;
    xhi[obase + d + half] = h2; xlo[obase + d + half] = l2;
}

// ---------------- batched prep ---------------------------------------------------
__global__ __launch_bounds__(256) void prep_kernel(
    const float* __restrict__ hid, bf16* __restrict__ hhi, bf16* __restrict__ hlo,
    const float* __restrict__ Wq, const float* __restrict__ Wk,
    const float* __restrict__ Wv, const float* __restrict__ Wo,
    bf16* __restrict__ wTh, bf16* __restrict__ wTl,
    bf16* __restrict__ woh, bf16* __restrict__ wol)
{
    __shared__ float tile[32][33];
    int bid = blockIdx.x;
    int tid = threadIdx.x;

    if (bid < 8192) {
        convert_body(hid, hhi, hlo, bid * 256 + tid, (BB*SS*HIDD) / 4);
    } else if (bid < 12288) {
        int t = bid - 8192;
        tr_body(tile, Wq, wTh, wTl, HIDD, NHH*HDD, t % 64, t / 64, tid);
    } else if (bid < 12800) {
        int t = bid - 12288;
        tr_body(tile, Wk, wTh + (size_t)HIDD*HIDD, wTl + (size_t)HIDD*HIDD,
                HIDD, HDD, t % 8, t / 8, tid);
    } else if (bid < 13312) {
        int t = bid - 12800;
        tr_body(tile, Wv, wTh + (size_t)2304*HIDD, wTl + (size_t)2304*HIDD,
                HIDD, HDD, t % 8, t / 8, tid);
    } else {
        int t = bid - 13312;
        tr_body(tile, Wo, woh, wol, NHH*HDD, HIDD, t % 64, t / 64, tid);
    }
}

// ---------------- batched mid ------------------------------------------------------
__global__ __launch_bounds__(256) void mid_kernel(
    const float* __restrict__ qkvf, const int* __restrict__ pos,
    bf16* __restrict__ qhi, bf16* __restrict__ qlo,
    bf16* __restrict__ khi, bf16* __restrict__ klo,
    bf16* __restrict__ vth, bf16* __restrict__ vtl)
{
    __shared__ float tile[32][33];
    int bid = blockIdx.x;
    int tid = threadIdx.x;

    if (bid < 16384) {
        rope_body(qkvf, pos, qhi, qlo, NHH, 2560, bid * 256 + tid);
    } else if (bid < 18432) {
        rope_body(qkvf + 2048, pos, khi, klo, 1, 2560, (bid - 16384) * 256 + tid);
    } else {
        int t = bid - 18432;
        int bx = t % 8;
        int by = (t / 8) % 64;
        int bz = t / (8 * 64);
        tr_body(tile, qkvf + 2304 + (size_t)bz * SS * 2560,
                vth + (size_t)bz * HDD * SS, vtl + (size_t)bz * HDD * SS,
                SS, 2560, bx, by, tid);
    }
}

// ---------------- causal softmax -----------------------------------------------
__global__ __launch_bounds__(256) void softmax_kernel(
    const float* __restrict__ scores,
    float* __restrict__ out, bf16* __restrict__ ohi, bf16* __restrict__ olo,
    float scale)
{
    const int row = blockIdx.x;
    const int q  = row % SS;
    const float4* srow = reinterpret_cast<const float4*>(scores + (size_t)row * SS);
    const int k4max = (((q >> 7) + 1) << 7) >> 2;

    const int tid = threadIdx.x;
    float4 v[2];
    float mx = -INFINITY;
#pragma unroll
    for (int i = 0; i < 2; i++) {
        int k4 = tid + i * 256;
        if (k4 < k4max) {
            float4 s4 = srow[k4];
            int kb = 4 * k4;
            v[i].x = (kb + 0 <= q) ? s4.x * scale : -INFINITY;
            v[i].y = (kb + 1 <= q) ? s4.y * scale : -INFINITY;
            v[i].z = (kb + 2 <= q) ? s4.z * scale : -INFINITY;
            v[i].w = (kb + 3 <= q) ? s4.w * scale : -INFINITY;
            mx = fmaxf(mx, fmaxf(fmaxf(v[i].x, v[i].y), fmaxf(v[i].z, v[i].w)));
        } else {
            v[i] = make_float4(-INFINITY, -INFINITY, -INFINITY, -INFINITY);
        }
    }

    __shared__ float red[32];
#pragma unroll
    for (int o = 16; o > 0; o >>= 1)
        mx = fmaxf(mx, __shfl_xor_sync(0xFFFFFFFF, mx, o));
    if ((tid & 31) == 0) red[tid >> 5] = mx;
    __syncthreads();
    if (tid < 32) {
        float m = (tid < 8) ? red[tid] : -INFINITY;
#pragma unroll
        for (int o = 4; o > 0; o >>= 1)
            m = fmaxf(m, __shfl_xor_sync(0xFFFFFFFF, m, o));
        if (tid == 0) red[0] = m;
    }
    __syncthreads();
    mx = red[0];
    __syncthreads();

    float sum = 0.f;
#pragma unroll
    for (int i = 0; i < 2; i++) {
        v[i].x = __expf(v[i].x - mx);
        v[i].y = __expf(v[i].y - mx);
        v[i].z = __expf(v[i].z - mx);
        v[i].w = __expf(v[i].w - mx);
        sum += (v[i].x + v[i].y) + (v[i].z + v[i].w);
    }
#pragma unroll
    for (int o = 16; o > 0; o >>= 1)
        sum += __shfl_xor_sync(0xFFFFFFFF, sum, o);
    if ((tid & 31) == 0) red[tid >> 5] = sum;
    __syncthreads();
    if (tid < 32) {
        float s = (tid < 8) ? red[tid] : 0.f;
#pragma unroll
        for (int o = 4; o > 0; o >>= 1)
            s += __shfl_xor_sync(0xFFFFFFFF, s, o);
        if (tid == 0) red[0] = s;
    }
    __syncthreads();
    float inv = 1.0f / red[0];

    float4* orow = reinterpret_cast<float4*>(out + (size_t)row * SS);
    uint2* hrow = reinterpret_cast<uint2*>(ohi + (size_t)row * SS);
    uint2* lrow = reinterpret_cast<uint2*>(olo + (size_t)row * SS);
#pragma unroll
    for (int i = 0; i < 2; i++) {
        int k4 = tid + i * 256;
        if (k4 < k4max) {
            float4 p = make_float4(v[i].x * inv, v[i].y * inv,
                                   v[i].z * inv, v[i].w * inv);
            orow[k4] = p;
            bf16 h0,l0,h1,l1,h2,l2,h3,l3;
            splitf(p.x,h0,l0); splitf(p.y,h1,l1); splitf(p.z,h2,l2); splitf(p.w,h3,l3);
            hrow[k4] = make_uint2(pack2(h0,h1), pack2(h2,h3));
            lrow[k4] = make_uint2(pack2(l0,l1), pack2(l2,l3));
        } else {
            orow[k4] = make_float4(0.f, 0.f, 0.f, 0.f);
        }
    }
}

// ---------------- launch -------------------------------------------------------
extern "C" void kernel_launch(void* const* d_in, const int* in_sizes, int n_in,
                              void* d_out, int out_size)
{
    const float* hid  = (const float*)d_in[0];
    const int*   pos  = (const int*)d_in[2];
    const float* Wq   = (const float*)d_in[3];
    const float* Wk   = (const float*)d_in[4];
    const float* Wv   = (const float*)d_in[5];
    const float* Wo   = (const float*)d_in[6];
    float* out = (float*)d_out;

    float *qkvf, *scores;
    bf16 *hhi,*hlo,*wTh,*wTl,*woh,*wol;
    bf16 *qhi,*qlo,*khi,*klo,*vth,*vtl,*ahi,*alo,*chi,*clo;
    cudaGetSymbolAddress((void**)&qkvf, g_qkvf);
    cudaGetSymbolAddress((void**)&scores, g_scores);
    cudaGetSymbolAddress((void**)&hhi, g_hhi);
    cudaGetSymbolAddress((void**)&hlo, g_hlo);
    cudaGetSymbolAddress((void**)&wTh, g_wT_hi);
    cudaGetSymbolAddress((void**)&wTl, g_wT_lo);
    cudaGetSymbolAddress((void**)&woh, g_woT_hi);
    cudaGetSymbolAddress((void**)&wol, g_woT_lo);
    cudaGetSymbolAddress((void**)&qhi, g_qhi);
    cudaGetSymbolAddress((void**)&qlo, g_qlo);
    cudaGetSymbolAddress((void**)&khi, g_khi);
    cudaGetSymbolAddress((void**)&klo, g_klo);
    cudaGetSymbolAddress((void**)&vth, g_vthi);
    cudaGetSymbolAddress((void**)&vtl, g_vtlo);
    cudaGetSymbolAddress((void**)&ahi, g_ahi);
    cudaGetSymbolAddress((void**)&alo, g_alo);
    cudaGetSymbolAddress((void**)&chi, g_chi);
    cudaGetSymbolAddress((void**)&clo, g_clo);

    constexpr int SMEM_512 = 2 * (2 * 16384 + 2 * 256 * 128);  // 196608
    cudaFuncSetAttribute((const void*)gemm_bf16_512,
        cudaFuncAttributeMaxDynamicSharedMemorySize, SMEM_512);

    const long long OUT_ATT = (long long)BB * SS * HIDD;
    const long long OUT_W   = (long long)BB * NHH * SS * SS;
    float* attnp = ((long long)out_size >= OUT_ATT + OUT_W) ? (out + OUT_ATT)
                                                            : scores;

    const int M = BB * SS;
    dim3 t256(256);
    dim3 t512(512);

    prep_kernel<<<17408, t256>>>(hid, hhi, hlo, Wq, Wk, Wv, Wo,
                                 wTh, wTl, woh, wol);

    // fused QKV projection (512-thread)
    gemm_bf16_512<<<dim3(2560/256, M/128, 1), t512, SMEM_512>>>(
        hhi, hlo, wTh, wTl, qkvf, nullptr, nullptr,
        HIDD, HIDD, HIDD, 2560, 0,0,0,0,0,0, 1, 0);

    mid_kernel<<<19456, t256>>>(qkvf, pos, qhi, qlo, khi, klo, vth, vtl);

    // scores = Q @ K^T (512-thread, causal tile-skip)
    gemm_bf16_512<<<dim3(SS/256, SS/128, BB*NHH), t512, SMEM_512>>>(
        qhi, qlo, khi, klo, scores, nullptr, nullptr,
        HDD, NHH*HDD, HDD, SS,
        (long long)SS*NHH*HDD, HDD,
        (long long)SS*HDD, 0,
        (long long)NHH*SS*SS, (long long)SS*SS, NHH, 1);

    softmax_kernel<<<BB*NHH*SS, t256>>>(scores, attnp, ahi, alo,
                                        1.0f / sqrtf((float)HDD));

    // ctx = attn @ V (512-thread, bounded k, hi/lo epilogue)
    gemm_bf16_512<<<dim3(HDD/256, SS/128, BB*NHH), t512, SMEM_512>>>(
        ahi, alo, vth, vtl, nullptr, chi, clo,
        SS, SS, SS, NHH*HDD,
        (long long)NHH*SS*SS, (long long)SS*SS,
        (long long)HDD*SS, 0,
        (long long)SS*NHH*HDD, HDD, NHH, 2);

    // out = ctx @ Wo (512-thread)
    gemm_bf16_512<<<dim3(HIDD/256, M/128, 1), t512, SMEM_512>>>(
        chi, clo, woh, wol, out, nullptr, nullptr,
        NHH*HDD, NHH*HDD, NHH*HDD, HIDD, 0,0,0,0,0,0, 1, 0);
}

// round 16
// speedup vs baseline: 1.0295x; 1.0295x over previous
#include <cuda_runtime.h>
#include <cuda_bf16.h>
#include <math.h>
#include <stdint.h>

#define BB 2
#define SS 2048
#define HIDD 2048
#define NHH 8
#define NKVV 1
#define HDD 256

typedef __nv_bfloat16 bf16;

// ---------------- scratch (device globals; no allocation allowed) -----------
__device__ float g_qkvf[(size_t)BB * SS * 2560];
__device__ float g_scores[(size_t)BB * NHH * SS * SS];

__device__ bf16 g_hhi[(size_t)BB * SS * HIDD];
__device__ bf16 g_hlo[(size_t)BB * SS * HIDD];
__device__ bf16 g_wT_hi[(size_t)2560 * HIDD];
__device__ bf16 g_wT_lo[(size_t)2560 * HIDD];
__device__ bf16 g_woT_hi[(size_t)HIDD * NHH * HDD];
__device__ bf16 g_woT_lo[(size_t)HIDD * NHH * HDD];
__device__ bf16 g_qhi[(size_t)BB * SS * NHH * HDD];
__device__ bf16 g_qlo[(size_t)BB * SS * NHH * HDD];
__device__ bf16 g_khi[(size_t)BB * SS * HDD];
__device__ bf16 g_klo[(size_t)BB * SS * HDD];
__device__ bf16 g_vthi[(size_t)BB * HDD * SS];
__device__ bf16 g_vtlo[(size_t)BB * HDD * SS];
__device__ bf16 g_ahi[(size_t)BB * NHH * SS * SS];
__device__ bf16 g_alo[(size_t)BB * NHH * SS * SS];
__device__ bf16 g_chi[(size_t)BB * SS * NHH * HDD];
__device__ bf16 g_clo[(size_t)BB * SS * NHH * HDD];

// ---------------- PTX helpers -------------------------------------------------
__device__ __forceinline__ uint32_t smem_to_u32(const void* p) {
    uint32_t a;
    asm("{ .reg .u64 t; cvta.to.shared.u64 t, %1; cvt.u32.u64 %0, t; }"
        : "=r"(a) : "l"(p));
    return a;
}
#define CPA(dst, src) \
    asm volatile("cp.async.cg.shared.global [%0], [%1], 16;" :: "r"(dst), "l"(src))
#define CPC() asm volatile("cp.async.commit_group;" ::: "memory")
#define CPW(n) asm volatile("cp.async.wait_group %0;" :: "n"(n) : "memory")
#define LDSM4(r, addr) \
    asm volatile("ldmatrix.sync.aligned.m8n8.x4.shared.b16 {%0,%1,%2,%3}, [%4];" \
        : "=r"((r)[0]), "=r"((r)[1]), "=r"((r)[2]), "=r"((r)[3]) : "r"(addr))

__device__ __forceinline__ void mma16816(float* c, const uint32_t* a, const uint32_t* b) {
    asm volatile(
        "mma.sync.aligned.m16n8k16.row.col.f32.bf16.bf16.f32 "
        "{%0,%1,%2,%3}, {%4,%5,%6,%7}, {%8,%9}, {%0,%1,%2,%3};"
        : "+f"(c[0]), "+f"(c[1]), "+f"(c[2]), "+f"(c[3])
        : "r"(a[0]), "r"(a[1]), "r"(a[2]), "r"(a[3]), "r"(b[0]), "r"(b[1]));
}

__device__ __forceinline__ void splitf(float x, bf16& hi, bf16& lo) {
    hi = __float2bfloat16(x);
    lo = __float2bfloat16(x - __bfloat162float(hi));
}
__device__ __forceinline__ uint32_t pack2(bf16 a, bf16 b) {
    return (uint32_t)__bfloat16_as_ushort(a) | ((uint32_t)__bfloat16_as_ushort(b) << 16);
}

// ---------------- staging ------------------------------------------------------
template <int BN, int NTH>
__device__ __forceinline__ void stage_tiles(
    uint32_t stg, const bf16* Ah, const bf16* Al,
    const bf16* Bh, const bf16* Bl, int lda, int ldb, int tid)
{
    constexpr uint32_t ATB = 16384;
    constexpr uint32_t BTB = BN * 128;
#pragma unroll
    for (int it = 0; it < 1024 / NTH; ++it) {
        int id = tid + it * NTH;
        int row = id >> 3, cc = id & 7;
        uint32_t soff = (uint32_t)(row * 128 + ((cc ^ (row & 7)) << 4));
        size_t go = (size_t)row * lda + cc * 8;
        CPA(stg + soff,       Ah + go);
        CPA(stg + ATB + soff, Al + go);
    }
#pragma unroll
    for (int it = 0; it < (BN * 8) / NTH; ++it) {
        int id = tid + it * NTH;
        int row = id >> 3, cc = id & 7;
        uint32_t soff = (uint32_t)(row * 128 + ((cc ^ (row & 7)) << 4));
        size_t go = (size_t)row * ldb + cc * 8;
        CPA(stg + 2 * ATB + soff,       Bh + go);
        CPA(stg + 2 * ATB + BTB + soff, Bl + go);
    }
}

// ---------------- BN=128 GEMM, 256 threads, 3-stage (AV only; proven R14) -------
template <int BN, int STAGES>
__global__ __launch_bounds__(256) void gemm_bf16(
    const bf16* __restrict__ Ahi, const bf16* __restrict__ Alo,
    const bf16* __restrict__ Bhi, const bf16* __restrict__ Blo,
    float* __restrict__ Cf, bf16* __restrict__ Chi, bf16* __restrict__ Clo,
    int K, int lda, int ldb, int ldc,
    long long sAb, long long sAh, long long sBb, long long sBh,
    long long sCb, long long sCh, int nh, int causal)
{
    constexpr int WN = BN / 4;
    constexpr int NT = WN / 8;
    constexpr uint32_t ATB = 16384;
    constexpr uint32_t BTB = BN * 128;
    constexpr uint32_t STG = 2 * ATB + 2 * BTB;

    extern __shared__ char dsm[];
    const uint32_t sb = smem_to_u32(dsm);

    int by = blockIdx.y;
    if (causal) by = gridDim.y - 1 - by;
    const int bm = by * 128;
    const int bn = blockIdx.x * BN;
    if (causal == 1 && bn >= bm + 128) return;

    const int z = blockIdx.z;
    const int b = z / nh, h = z % nh;
    const size_t aoff = (size_t)b * sAb + (size_t)h * sAh;
    const size_t boff = (size_t)b * sBb + (size_t)h * sBh;
    const size_t coff = (size_t)b * sCb + (size_t)h * sCh;

    const int tid  = threadIdx.x;
    const int lane = tid & 31;
    const int wid  = tid >> 5;
    const int g = lane >> 2, t = lane & 3;
    const int m0 = (wid & 1) * 64;
    const int n0 = (wid >> 1) * WN;

    const bf16* Ah0 = Ahi + aoff + (size_t)bm * lda;
    const bf16* Al0 = Alo + aoff + (size_t)bm * lda;
    const bf16* Bh0 = Bhi + boff + (size_t)bn * ldb;
    const bf16* Bl0 = Blo + boff + (size_t)bn * ldb;

    float acc[4][NT][4];
#pragma unroll
    for (int i = 0; i < 4; i++)
#pragma unroll
        for (int j = 0; j < NT; j++)
#pragma unroll
            for (int r = 0; r < 4; r++) acc[i][j][r] = 0.f;

    int nchunks = K / 64;
    if (causal == 2) {
        int nc = (bm + 128) / 64;
        if (nc < nchunks) nchunks = nc;
    }

    const int arow = m0 + (lane & 15);
    const int akh  = lane >> 4;
    const int brow = n0 + ((lane >> 3) & 1) * 8 + (lane & 7);
    const int bkh  = lane >> 4;

#pragma unroll
    for (int s = 0; s < 2; ++s) {
        if (s < nchunks)
            stage_tiles<BN,256>(sb + (uint32_t)s * STG, Ah0 + s * 64, Al0 + s * 64,
                                Bh0 + s * 64, Bl0 + s * 64, lda, ldb, tid);
        CPC();
    }

    for (int c = 0; c < nchunks; ++c) {
        if (STAGES == 3) {
            CPW(1);
        } else {
            if (c + 1 < nchunks) CPW(1); else CPW(0);
        }
        __syncthreads();

        if (STAGES == 3) {
            int pf = c + 2;
            if (pf < nchunks)
                stage_tiles<BN,256>(sb + (uint32_t)(pf % 3) * STG,
                                    Ah0 + pf * 64, Al0 + pf * 64,
                                    Bh0 + pf * 64, Bl0 + pf * 64, lda, ldb, tid);
            CPC();
        }

        const uint32_t stg = sb + (uint32_t)(c % STAGES) * STG;
        const uint32_t aHi = stg, aLo = stg + ATB;
        const uint32_t bHi = stg + 2 * ATB, bLo = stg + 2 * ATB + BTB;

#pragma unroll
        for (int ks = 0; ks < 4; ++ks) {
            uint32_t ah[4][4], al[4][4], bfr[NT][2];
#pragma unroll
            for (int mt = 0; mt < 4; ++mt) {
                int row = arow + mt * 16;
                uint32_t off = (uint32_t)(row * 128 +
                    (((2 * ks + akh) ^ (row & 7)) << 4));
                LDSM4(ah[mt], aHi + off);
                LDSM4(al[mt], aLo + off);
            }
#pragma unroll
            for (int p = 0; p < NT / 2; ++p) {
                int row = brow + p * 16;
                uint32_t off = (uint32_t)(row * 128 +
                    (((2 * ks + bkh) ^ (row & 7)) << 4));
                uint32_t rh[4];
                LDSM4(rh, bHi + off);
                bfr[2 * p][0] = rh[0]; bfr[2 * p][1] = rh[2];
                bfr[2 * p + 1][0] = rh[1]; bfr[2 * p + 1][1] = rh[3];
            }
#pragma unroll
            for (int mt = 0; mt < 4; ++mt)
#pragma unroll
                for (int nt = 0; nt < NT; ++nt) {
                    mma16816(acc[mt][nt], ah[mt], bfr[nt]);
                    mma16816(acc[mt][nt], al[mt], bfr[nt]);
                }
#pragma unroll
            for (int p = 0; p < NT / 2; ++p) {
                int row = brow + p * 16;
                uint32_t off = (uint32_t)(row * 128 +
                    (((2 * ks + bkh) ^ (row & 7)) << 4));
                uint32_t rl[4];
                LDSM4(rl, bLo + off);
                bfr[2 * p][0] = rl[0]; bfr[2 * p][1] = rl[2];
                bfr[2 * p + 1][0] = rl[1]; bfr[2 * p + 1][1] = rl[3];
            }
#pragma unroll
            for (int mt = 0; mt < 4; ++mt)
#pragma unroll
                for (int nt = 0; nt < NT; ++nt)
                    mma16816(acc[mt][nt], ah[mt], bfr[nt]);
        }

        if (STAGES == 2) {
            __syncthreads();
            int pf = c + 2;
            if (pf < nchunks) {
                stage_tiles<BN,256>(sb + (uint32_t)(pf % 2) * STG,
                                    Ah0 + pf * 64, Al0 + pf * 64,
                                    Bh0 + pf * 64, Bl0 + pf * 64, lda, ldb, tid);
                CPC();
            }
        }
    }

#pragma unroll
    for (int mt = 0; mt < 4; ++mt) {
#pragma unroll
        for (int nt = 0; nt < NT; ++nt) {
            int row = bm + m0 + mt * 16 + g;
            int col = bn + n0 + nt * 8 + 2 * t;
            if (Cf) {
                *reinterpret_cast<float2*>(Cf + coff + (size_t)row * ldc + col) =
                    make_float2(acc[mt][nt][0], acc[mt][nt][1]);
                *reinterpret_cast<float2*>(Cf + coff + (size_t)(row + 8) * ldc + col) =
                    make_float2(acc[mt][nt][2], acc[mt][nt][3]);
            }
            if (Chi) {
                bf16 h0, l0, h1, l1;
                splitf(acc[mt][nt][0], h0, l0);
                splitf(acc[mt][nt][1], h1, l1);
                *reinterpret_cast<uint32_t*>(Chi + coff + (size_t)row * ldc + col) = pack2(h0, h1);
                *reinterpret_cast<uint32_t*>(Clo + coff + (size_t)row * ldc + col) = pack2(l0, l1);
                splitf(acc[mt][nt][2], h0, l0);
                splitf(acc[mt][nt][3], h1, l1);
                *reinterpret_cast<uint32_t*>(Chi + coff + (size_t)(row + 8) * ldc + col) = pack2(h0, h1);
                *reinterpret_cast<uint32_t*>(Clo + coff + (size_t)(row + 8) * ldc + col) = pack2(l0, l1);
            }
        }
    }
}

// ---------------- BN=256 GEMM, 512 threads (QK / Wo / proj; proven R15) ---------
__global__ __launch_bounds__(512) void gemm_bf16_512(
    const bf16* __restrict__ Ahi, const bf16* __restrict__ Alo,
    const bf16* __restrict__ Bhi, const bf16* __restrict__ Blo,
    float* __restrict__ Cf, bf16* __restrict__ Chi, bf16* __restrict__ Clo,
    int K, int lda, int ldb, int ldc,
    long long sAb, long long sAh, long long sBb, long long sBh,
    long long sCb, long long sCh, int nh, int causal)
{
    constexpr uint32_t ATB = 16384;
    constexpr uint32_t BTB = 256 * 128;
    constexpr uint32_t STG = 2 * ATB + 2 * BTB;

    extern __shared__ char dsm[];
    const uint32_t sb = smem_to_u32(dsm);

    int by = blockIdx.y;
    if (causal) by = gridDim.y - 1 - by;
    const int bm = by * 128;
    const int bn = blockIdx.x * 256;
    if (causal == 1 && bn >= bm + 128) return;

    const int z = blockIdx.z;
    const int b = z / nh, h = z % nh;
    const size_t aoff = (size_t)b * sAb + (size_t)h * sAh;
    const size_t boff = (size_t)b * sBb + (size_t)h * sBh;
    const size_t coff = (size_t)b * sCb + (size_t)h * sCh;

    const int tid  = threadIdx.x;
    const int lane = tid & 31;
    const int wid  = tid >> 5;
    const int g = lane >> 2, t = lane & 3;
    const int m0 = (wid & 3) * 32;
    const int n0 = (wid >> 2) * 64;

    const bf16* Ah0 = Ahi + aoff + (size_t)bm * lda;
    const bf16* Al0 = Alo + aoff + (size_t)bm * lda;
    const bf16* Bh0 = Bhi + boff + (size_t)bn * ldb;
    const bf16* Bl0 = Blo + boff + (size_t)bn * ldb;

    float acc[2][8][4];
#pragma unroll
    for (int i = 0; i < 2; i++)
#pragma unroll
        for (int j = 0; j < 8; j++)
#pragma unroll
            for (int r = 0; r < 4; r++) acc[i][j][r] = 0.f;

    int nchunks = K / 64;
    if (causal == 2) {
        int nc = (bm + 128) / 64;
        if (nc < nchunks) nchunks = nc;
    }

    const int arow = m0 + (lane & 15);
    const int akh  = lane >> 4;
    const int brow = n0 + ((lane >> 3) & 1) * 8 + (lane & 7);
    const int bkh  = lane >> 4;

#pragma unroll
    for (int s = 0; s < 2; ++s) {
        if (s < nchunks)
            stage_tiles<256,512>(sb + (uint32_t)s * STG, Ah0 + s * 64, Al0 + s * 64,
                                 Bh0 + s * 64, Bl0 + s * 64, lda, ldb, tid);
        CPC();
    }

    for (int c = 0; c < nchunks; ++c) {
        if (c + 1 < nchunks) CPW(1); else CPW(0);
        __syncthreads();

        const uint32_t stg = sb + (uint32_t)(c & 1) * STG;
        const uint32_t aHi = stg, aLo = stg + ATB;
        const uint32_t bHi = stg + 2 * ATB, bLo = stg + 2 * ATB + BTB;

#pragma unroll
        for (int ks = 0; ks < 4; ++ks) {
            uint32_t af[2][4], bfr[8][2];

#pragma unroll
            for (int mt = 0; mt < 2; ++mt) {
                int row = arow + mt * 16;
                uint32_t off = (uint32_t)(row * 128 +
                    (((2 * ks + akh) ^ (row & 7)) << 4));
                LDSM4(af[mt], aHi + off);
            }
#pragma unroll
            for (int p = 0; p < 4; ++p) {
                int row = brow + p * 16;
                uint32_t off = (uint32_t)(row * 128 +
                    (((2 * ks + bkh) ^ (row & 7)) << 4));
                uint32_t rh[4];
                LDSM4(rh, bHi + off);
                bfr[2 * p][0] = rh[0]; bfr[2 * p][1] = rh[2];
                bfr[2 * p + 1][0] = rh[1]; bfr[2 * p + 1][1] = rh[3];
            }
#pragma unroll
            for (int mt = 0; mt < 2; ++mt)
#pragma unroll
                for (int nt = 0; nt < 8; ++nt)
                    mma16816(acc[mt][nt], af[mt], bfr[nt]);

#pragma unroll
            for (int mt = 0; mt < 2; ++mt) {
                int row = arow + mt * 16;
                uint32_t off = (uint32_t)(row * 128 +
                    (((2 * ks + akh) ^ (row & 7)) << 4));
                LDSM4(af[mt], aLo + off);
            }
#pragma unroll
            for (int mt = 0; mt < 2; ++mt)
#pragma unroll
                for (int nt = 0; nt < 8; ++nt)
                    mma16816(acc[mt][nt], af[mt], bfr[nt]);

#pragma unroll
            for (int mt = 0; mt < 2; ++mt) {
                int row = arow + mt * 16;
                uint32_t off = (uint32_t)(row * 128 +
                    (((2 * ks + akh) ^ (row & 7)) << 4));
                LDSM4(af[mt], aHi + off);
            }
#pragma unroll
            for (int p = 0; p < 4; ++p) {
                int row = brow + p * 16;
                uint32_t off = (uint32_t)(row * 128 +
                    (((2 * ks + bkh) ^ (row & 7)) << 4));
                uint32_t rl[4];
                LDSM4(rl, bLo + off);
                bfr[2 * p][0] = rl[0]; bfr[2 * p][1] = rl[2];
                bfr[2 * p + 1][0] = rl[1]; bfr[2 * p + 1][1] = rl[3];
            }
#pragma unroll
            for (int mt = 0; mt < 2; ++mt)
#pragma unroll
                for (int nt = 0; nt < 8; ++nt)
                    mma16816(acc[mt][nt], af[mt], bfr[nt]);
        }

        __syncthreads();
        int pf = c + 2;
        if (pf < nchunks) {
            stage_tiles<256,512>(sb + (uint32_t)(pf & 1) * STG,
                                 Ah0 + pf * 64, Al0 + pf * 64,
                                 Bh0 + pf * 64, Bl0 + pf * 64, lda, ldb, tid);
            CPC();
        }
    }

#pragma unroll
    for (int mt = 0; mt < 2; ++mt) {
#pragma unroll
        for (int nt = 0; nt < 8; ++nt) {
            int row = bm + m0 + mt * 16 + g;
            int col = bn + n0 + nt * 8 + 2 * t;
            if (Cf) {
                *reinterpret_cast<float2*>(Cf + coff + (size_t)row * ldc + col) =
                    make_float2(acc[mt][nt][0], acc[mt][nt][1]);
                *reinterpret_cast<float2*>(Cf + coff + (size_t)(row + 8) * ldc + col) =
                    make_float2(acc[mt][nt][2], acc[mt][nt][3]);
            }
            if (Chi) {
                bf16 h0, l0, h1, l1;
                splitf(acc[mt][nt][0], h0, l0);
                splitf(acc[mt][nt][1], h1, l1);
                *reinterpret_cast<uint32_t*>(Chi + coff + (size_t)row * ldc + col) = pack2(h0, h1);
                *reinterpret_cast<uint32_t*>(Clo + coff + (size_t)row * ldc + col) = pack2(l0, l1);
                splitf(acc[mt][nt][2], h0, l0);
                splitf(acc[mt][nt][3], h1, l1);
                *reinterpret_cast<uint32_t*>(Chi + coff + (size_t)(row + 8) * ldc + col) = pack2(h0, h1);
                *reinterpret_cast<uint32_t*>(Clo + coff + (size_t)(row + 8) * ldc + col) = pack2(l0, l1);
            }
        }
    }
}

// ---------------- elementwise bodies (proven) ----------------------------------
__device__ __forceinline__ void convert_body(
    const float* __restrict__ in, bf16* __restrict__ hi, bf16* __restrict__ lo,
    int idx, int n4)
{
    if (idx >= n4) return;
    float4 f = reinterpret_cast<const float4*>(in)[idx];
    bf16 h0,l0,h1,l1,h2,l2,h3,l3;
    splitf(f.x,h0,l0); splitf(f.y,h1,l1); splitf(f.z,h2,l2); splitf(f.w,h3,l3);
    reinterpret_cast<uint2*>(hi)[idx] = make_uint2(pack2(h0,h1), pack2(h2,h3));
    reinterpret_cast<uint2*>(lo)[idx] = make_uint2(pack2(l0,l1), pack2(l2,l3));
}

__device__ __forceinline__ void tr_body(
    float (*tile)[33],
    const float* __restrict__ in, bf16* __restrict__ ohi, bf16* __restrict__ olo,
    int R, int Cstride, int bx, int by, int tid)
{
    int c0 = bx * 32, r0 = by * 32;
    {
        int lr  = tid >> 3;
        int lc4 = (tid & 7) * 4;
        float4 f = *reinterpret_cast<const float4*>(
            in + (size_t)(r0 + lr) * Cstride + c0 + lc4);
        tile[lr][lc4 + 0] = f.x;
        tile[lr][lc4 + 1] = f.y;
        tile[lr][lc4 + 2] = f.z;
        tile[lr][lc4 + 3] = f.w;
    }
    __syncthreads();
    {
        int c  = tid >> 3;
        int rg = (tid & 7) * 4;
        bf16 h[4], l[4];
#pragma unroll
        for (int j = 0; j < 4; ++j)
            splitf(tile[rg + j][c], h[j], l[j]);
        size_t o = (size_t)(c0 + c) * R + r0 + rg;
        *reinterpret_cast<uint2*>(ohi + o) = make_uint2(pack2(h[0],h[1]), pack2(h[2],h[3]));
        *reinterpret_cast<uint2*>(olo + o) = make_uint2(pack2(l[0],l[1]), pack2(l[2],l[3]));
    }
}

__device__ __forceinline__ void rope_body(
    const float* __restrict__ x, const int* __restrict__ pos_ids,
    bf16* __restrict__ xhi, bf16* __restrict__ xlo,
    int nheads, int in_stride, int idx)
{
    const int half = HDD / 2;
    int total = BB * SS * nheads * half;
    if (idx >= total) return;
    int d = idx % half;
    int tt = idx / half;
    int h = tt % nheads;
    int s = (tt / nheads) % SS;
    int b = tt / (nheads * SS);

    float pos = (float)pos_ids[b * SS + s];
    float inv = exp2f(-(float)d * 0.103810253f);
    float ang = pos * inv;
    float c = cosf(ang), sn = sinf(ang);

    size_t ibase = (size_t)(b * SS + s) * in_stride + h * HDD;
    float x1 = x[ibase + d];
    float x2 = x[ibase + d + half];
    float r1 = x1 * c - x2 * sn;
    float r2 = x2 * c + x1 * sn;
    bf16 h1, l1, h2, l2;
    splitf(r1, h1, l1);
    splitf(r2, h2, l2);
    size_t obase = ((size_t)(b * SS + s) * nheads + h) * HDD;
    xhi[obase + d] = h1;        xlo[obase + d] = l1;
    xhi[obase + d + half] = h2; xlo[obase + d + half] = l2;
}

// ---------------- batched prep ---------------------------------------------------
__global__ __launch_bounds__(256) void prep_kernel(
    const float* __restrict__ hid, bf16* __restrict__ hhi, bf16* __restrict__ hlo,
    const float* __restrict__ Wq, const float* __restrict__ Wk,
    const float* __restrict__ Wv, const float* __restrict__ Wo,
    bf16* __restrict__ wTh, bf16* __restrict__ wTl,
    bf16* __restrict__ woh, bf16* __restrict__ wol)
{
    __shared__ float tile[32][33];
    int bid = blockIdx.x;
    int tid = threadIdx.x;

    if (bid < 8192) {
        convert_body(hid, hhi, hlo, bid * 256 + tid, (BB*SS*HIDD) / 4);
    } else if (bid < 12288) {
        int t = bid - 8192;
        tr_body(tile, Wq, wTh, wTl, HIDD, NHH*HDD, t % 64, t / 64, tid);
    } else if (bid < 12800) {
        int t = bid - 12288;
        tr_body(tile, Wk, wTh + (size_t)HIDD*HIDD, wTl + (size_t)HIDD*HIDD,
                HIDD, HDD, t % 8, t / 8, tid);
    } else if (bid < 13312) {
        int t = bid - 12800;
        tr_body(tile, Wv, wTh + (size_t)2304*HIDD, wTl + (size_t)2304*HIDD,
                HIDD, HDD, t % 8, t / 8, tid);
    } else {
        int t = bid - 13312;
        tr_body(tile, Wo, woh, wol, NHH*HDD, HIDD, t % 64, t / 64, tid);
    }
}

// ---------------- batched mid ------------------------------------------------------
__global__ __launch_bounds__(256) void mid_kernel(
    const float* __restrict__ qkvf, const int* __restrict__ pos,
    bf16* __restrict__ qhi, bf16* __restrict__ qlo,
    bf16* __restrict__ khi, bf16* __restrict__ klo,
    bf16* __restrict__ vth, bf16* __restrict__ vtl)
{
    __shared__ float tile[32][33];
    int bid = blockIdx.x;
    int tid = threadIdx.x;

    if (bid < 16384) {
        rope_body(qkvf, pos, qhi, qlo, NHH, 2560, bid * 256 + tid);
    } else if (bid < 18432) {
        rope_body(qkvf + 2048, pos, khi, klo, 1, 2560, (bid - 16384) * 256 + tid);
    } else {
        int t = bid - 18432;
        int bx = t % 8;
        int by = (t / 8) % 64;
        int bz = t / (8 * 64);
        tr_body(tile, qkvf + 2304 + (size_t)bz * SS * 2560,
                vth + (size_t)bz * HDD * SS, vtl + (size_t)bz * HDD * SS,
                SS, 2560, bx, by, tid);
    }
}

// ---------------- causal softmax -----------------------------------------------
__global__ __launch_bounds__(256) void softmax_kernel(
    const float* __restrict__ scores,
    float* __restrict__ out, bf16* __restrict__ ohi, bf16* __restrict__ olo,
    float scale)
{
    const int row = blockIdx.x;
    const int q  = row % SS;
    const float4* srow = reinterpret_cast<const float4*>(scores + (size_t)row * SS);
    const int k4max = (((q >> 7) + 1) << 7) >> 2;

    const int tid = threadIdx.x;
    float4 v[2];
    float mx = -INFINITY;
#pragma unroll
    for (int i = 0; i < 2; i++) {
        int k4 = tid + i * 256;
        if (k4 < k4max) {
            float4 s4 = srow[k4];
            int kb = 4 * k4;
            v[i].x = (kb + 0 <= q) ? s4.x * scale : -INFINITY;
            v[i].y = (kb + 1 <= q) ? s4.y * scale : -INFINITY;
            v[i].z = (kb + 2 <= q) ? s4.z * scale : -INFINITY;
            v[i].w = (kb + 3 <= q) ? s4.w * scale : -INFINITY;
            mx = fmaxf(mx, fmaxf(fmaxf(v[i].x, v[i].y), fmaxf(v[i].z, v[i].w)));
        } else {
            v[i] = make_float4(-INFINITY, -INFINITY, -INFINITY, -INFINITY);
        }
    }

    __shared__ float red[32];
#pragma unroll
    for (int o = 16; o > 0; o >>= 1)
        mx = fmaxf(mx, __shfl_xor_sync(0xFFFFFFFF, mx, o));
    if ((tid & 31) == 0) red[tid >> 5] = mx;
    __syncthreads();
    if (tid < 32) {
        float m = (tid < 8) ? red[tid] : -INFINITY;
#pragma unroll
        for (int o = 4; o > 0; o >>= 1)
            m = fmaxf(m, __shfl_xor_sync(0xFFFFFFFF, m, o));
        if (tid == 0) red[0] = m;
    }
    __syncthreads();
    mx = red[0];
    __syncthreads();

    float sum = 0.f;
#pragma unroll
    for (int i = 0; i < 2; i++) {
        v[i].x = __expf(v[i].x - mx);
        v[i].y = __expf(v[i].y - mx);
        v[i].z = __expf(v[i].z - mx);
        v[i].w = __expf(v[i].w - mx);
        sum += (v[i].x + v[i].y) + (v[i].z + v[i].w);
    }
#pragma unroll
    for (int o = 16; o > 0; o >>= 1)
        sum += __shfl_xor_sync(0xFFFFFFFF, sum, o);
    if ((tid & 31) == 0) red[tid >> 5] = sum;
    __syncthreads();
    if (tid < 32) {
        float s = (tid < 8) ? red[tid] : 0.f;
#pragma unroll
        for (int o = 4; o > 0; o >>= 1)
            s += __shfl_xor_sync(0xFFFFFFFF, s, o);
        if (tid == 0) red[0] = s;
    }
    __syncthreads();
    float inv = 1.0f / red[0];

    float4* orow = reinterpret_cast<float4*>(out + (size_t)row * SS);
    uint2* hrow = reinterpret_cast<uint2*>(ohi + (size_t)row * SS);
    uint2* lrow = reinterpret_cast<uint2*>(olo + (size_t)row * SS);
#pragma unroll
    for (int i = 0; i < 2; i++) {
        int k4 = tid + i * 256;
        if (k4 < k4max) {
            float4 p = make_float4(v[i].x * inv, v[i].y * inv,
                                   v[i].z * inv, v[i].w * inv);
            orow[k4] = p;
            bf16 h0,l0,h1,l1,h2,l2,h3,l3;
            splitf(p.x,h0,l0); splitf(p.y,h1,l1); splitf(p.z,h2,l2); splitf(p.w,h3,l3);
            hrow[k4] = make_uint2(pack2(h0,h1), pack2(h2,h3));
            lrow[k4] = make_uint2(pack2(l0,l1), pack2(l2,l3));
        } else {
            orow[k4] = make_float4(0.f, 0.f, 0.f, 0.f);
        }
    }
}

// ---------------- launch -------------------------------------------------------
extern "C" void kernel_launch(void* const* d_in, const int* in_sizes, int n_in,
                              void* d_out, int out_size)
{
    const float* hid  = (const float*)d_in[0];
    const int*   pos  = (const int*)d_in[2];
    const float* Wq   = (const float*)d_in[3];
    const float* Wk   = (const float*)d_in[4];
    const float* Wv   = (const float*)d_in[5];
    const float* Wo   = (const float*)d_in[6];
    float* out = (float*)d_out;

    float *qkvf, *scores;
    bf16 *hhi,*hlo,*wTh,*wTl,*woh,*wol;
    bf16 *qhi,*qlo,*khi,*klo,*vth,*vtl,*ahi,*alo,*chi,*clo;
    cudaGetSymbolAddress((void**)&qkvf, g_qkvf);
    cudaGetSymbolAddress((void**)&scores, g_scores);
    cudaGetSymbolAddress((void**)&hhi, g_hhi);
    cudaGetSymbolAddress((void**)&hlo, g_hlo);
    cudaGetSymbolAddress((void**)&wTh, g_wT_hi);
    cudaGetSymbolAddress((void**)&wTl, g_wT_lo);
    cudaGetSymbolAddress((void**)&woh, g_woT_hi);
    cudaGetSymbolAddress((void**)&wol, g_woT_lo);
    cudaGetSymbolAddress((void**)&qhi, g_qhi);
    cudaGetSymbolAddress((void**)&qlo, g_qlo);
    cudaGetSymbolAddress((void**)&khi, g_khi);
    cudaGetSymbolAddress((void**)&klo, g_klo);
    cudaGetSymbolAddress((void**)&vth, g_vthi);
    cudaGetSymbolAddress((void**)&vtl, g_vtlo);
    cudaGetSymbolAddress((void**)&ahi, g_ahi);
    cudaGetSymbolAddress((void**)&alo, g_alo);
    cudaGetSymbolAddress((void**)&chi, g_chi);
    cudaGetSymbolAddress((void**)&clo, g_clo);

    constexpr int SMEM_3S_128 = 3 * (2 * 16384 + 2 * 128 * 128);  // 196608
    constexpr int SMEM_512    = 2 * (2 * 16384 + 2 * 256 * 128);  // 196608
    cudaFuncSetAttribute((const void*)gemm_bf16<128,3>,
        cudaFuncAttributeMaxDynamicSharedMemorySize, SMEM_3S_128);
    cudaFuncSetAttribute((const void*)gemm_bf16_512,
        cudaFuncAttributeMaxDynamicSharedMemorySize, SMEM_512);

    const long long OUT_ATT = (long long)BB * SS * HIDD;
    const long long OUT_W   = (long long)BB * NHH * SS * SS;
    float* attnp = ((long long)out_size >= OUT_ATT + OUT_W) ? (out + OUT_ATT)
                                                            : scores;

    const int M = BB * SS;
    dim3 t256(256);
    dim3 t512(512);

    prep_kernel<<<17408, t256>>>(hid, hhi, hlo, Wq, Wk, Wv, Wo,
                                 wTh, wTl, woh, wol);

    // fused QKV projection (512-thread; dense, uniform K)
    gemm_bf16_512<<<dim3(2560/256, M/128, 1), t512, SMEM_512>>>(
        hhi, hlo, wTh, wTl, qkvf, nullptr, nullptr,
        HIDD, HIDD, HIDD, 2560, 0,0,0,0,0,0, 1, 0);

    mid_kernel<<<19456, t256>>>(qkvf, pos, qhi, qlo, khi, klo, vth, vtl);

    // scores = Q @ K^T (512-thread, causal tile-skip)
    gemm_bf16_512<<<dim3(SS/256, SS/128, BB*NHH), t512, SMEM_512>>>(
        qhi, qlo, khi, klo, scores, nullptr, nullptr,
        HDD, NHH*HDD, HDD, SS,
        (long long)SS*NHH*HDD, HDD,
        (long long)SS*HDD, 0,
        (long long)NHH*SS*SS, (long long)SS*SS, NHH, 1);

    softmax_kernel<<<BB*NHH*SS, t256>>>(scores, attnp, ahi, alo,
                                        1.0f / sqrtf((float)HDD));

    // ctx = attn @ V (BN=128, 256-thread, 3-stage — better load balance)
    gemm_bf16<128,3><<<dim3(HDD/128, SS/128, BB*NHH), t256, SMEM_3S_128>>>(
        ahi, alo, vth, vtl, nullptr, chi, clo,
        SS, SS, SS, NHH*HDD,
        (long long)NHH*SS*SS, (long long)SS*SS,
        (long long)HDD*SS, 0,
        (long long)SS*NHH*HDD, HDD, NHH, 2);

    // out = ctx @ Wo (512-thread)
    gemm_bf16_512<<<dim3(HIDD/256, M/128, 1), t512, SMEM_512>>>(
        chi, clo, woh, wol, out, nullptr, nullptr,
        NHH*HDD, NHH*HDD, NHH*HDD, HIDD, 0,0,0,0,0,0, 1, 0);
}

// round 17
// speedup vs baseline: 1.0677x; 1.0371x over previous
#include <cuda_runtime.h>
#include <cuda_bf16.h>
#include <math.h>
#include <stdint.h>

#define BB 2
#define SS 2048
#define HIDD 2048
#define NHH 8
#define NKVV 1
#define HDD 256

typedef __nv_bfloat16 bf16;

// ---------------- scratch (device globals; no allocation allowed) -----------
__device__ float g_qkvf[(size_t)BB * SS * 2560];
__device__ float g_scores[(size_t)BB * NHH * SS * SS];

__device__ bf16 g_hhi[(size_t)BB * SS * HIDD];
__device__ bf16 g_hlo[(size_t)BB * SS * HIDD];
__device__ bf16 g_wT_hi[(size_t)2560 * HIDD];
__device__ bf16 g_wT_lo[(size_t)2560 * HIDD];
__device__ bf16 g_woT_hi[(size_t)HIDD * NHH * HDD];
__device__ bf16 g_woT_lo[(size_t)HIDD * NHH * HDD];
__device__ bf16 g_qhi[(size_t)BB * SS * NHH * HDD];
__device__ bf16 g_qlo[(size_t)BB * SS * NHH * HDD];
__device__ bf16 g_khi[(size_t)BB * SS * HDD];
__device__ bf16 g_klo[(size_t)BB * SS * HDD];
__device__ bf16 g_vthi[(size_t)BB * HDD * SS];
__device__ bf16 g_vtlo[(size_t)BB * HDD * SS];
__device__ bf16 g_ahi[(size_t)BB * NHH * SS * SS];
__device__ bf16 g_alo[(size_t)BB * NHH * SS * SS];
__device__ bf16 g_chi[(size_t)BB * SS * NHH * HDD];
__device__ bf16 g_clo[(size_t)BB * SS * NHH * HDD];

// ---------------- PTX helpers -------------------------------------------------
__device__ __forceinline__ uint32_t smem_to_u32(const void* p) {
    uint32_t a;
    asm("{ .reg .u64 t; cvta.to.shared.u64 t, %1; cvt.u32.u64 %0, t; }"
        : "=r"(a) : "l"(p));
    return a;
}
#define CPA(dst, src) \
    asm volatile("cp.async.cg.shared.global [%0], [%1], 16;" :: "r"(dst), "l"(src))
#define CPC() asm volatile("cp.async.commit_group;" ::: "memory")
#define CPW(n) asm volatile("cp.async.wait_group %0;" :: "n"(n) : "memory")
#define LDSM4(r, addr) \
    asm volatile("ldmatrix.sync.aligned.m8n8.x4.shared.b16 {%0,%1,%2,%3}, [%4];" \
        : "=r"((r)[0]), "=r"((r)[1]), "=r"((r)[2]), "=r"((r)[3]) : "r"(addr))

__device__ __forceinline__ void mma16816(float* c, const uint32_t* a, const uint32_t* b) {
    asm volatile(
        "mma.sync.aligned.m16n8k16.row.col.f32.bf16.bf16.f32 "
        "{%0,%1,%2,%3}, {%4,%5,%6,%7}, {%8,%9}, {%0,%1,%2,%3};"
        : "+f"(c[0]), "+f"(c[1]), "+f"(c[2]), "+f"(c[3])
        : "r"(a[0]), "r"(a[1]), "r"(a[2]), "r"(a[3]), "r"(b[0]), "r"(b[1]));
}

__device__ __forceinline__ void splitf(float x, bf16& hi, bf16& lo) {
    hi = __float2bfloat16(x);
    lo = __float2bfloat16(x - __bfloat162float(hi));
}
__device__ __forceinline__ uint32_t pack2(bf16 a, bf16 b) {
    return (uint32_t)__bfloat16_as_ushort(a) | ((uint32_t)__bfloat16_as_ushort(b) << 16);
}

// ---------------- staging ------------------------------------------------------
template <int BN, int NTH>
__device__ __forceinline__ void stage_tiles(
    uint32_t stg, const bf16* Ah, const bf16* Al,
    const bf16* Bh, const bf16* Bl, int lda, int ldb, int tid)
{
    constexpr uint32_t ATB = 16384;
    constexpr uint32_t BTB = BN * 128;
#pragma unroll
    for (int it = 0; it < 1024 / NTH; ++it) {
        int id = tid + it * NTH;
        int row = id >> 3, cc = id & 7;
        uint32_t soff = (uint32_t)(row * 128 + ((cc ^ (row & 7)) << 4));
        size_t go = (size_t)row * lda + cc * 8;
        CPA(stg + soff,       Ah + go);
        CPA(stg + ATB + soff, Al + go);
    }
#pragma unroll
    for (int it = 0; it < (BN * 8) / NTH; ++it) {
        int id = tid + it * NTH;
        int row = id >> 3, cc = id & 7;
        uint32_t soff = (uint32_t)(row * 128 + ((cc ^ (row & 7)) << 4));
        size_t go = (size_t)row * ldb + cc * 8;
        CPA(stg + 2 * ATB + soff,       Bh + go);
        CPA(stg + 2 * ATB + BTB + soff, Bl + go);
    }
}

// ---------------- BN=128 GEMM, 256 threads, 3-stage (proj + AV; proven R14) -----
template <int BN, int STAGES>
__global__ __launch_bounds__(256) void gemm_bf16(
    const bf16* __restrict__ Ahi, const bf16* __restrict__ Alo,
    const bf16* __restrict__ Bhi, const bf16* __restrict__ Blo,
    float* __restrict__ Cf, bf16* __restrict__ Chi, bf16* __restrict__ Clo,
    int K, int lda, int ldb, int ldc,
    long long sAb, long long sAh, long long sBb, long long sBh,
    long long sCb, long long sCh, int nh, int causal)
{
    constexpr int WN = BN / 4;
    constexpr int NT = WN / 8;
    constexpr uint32_t ATB = 16384;
    constexpr uint32_t BTB = BN * 128;
    constexpr uint32_t STG = 2 * ATB + 2 * BTB;

    extern __shared__ char dsm[];
    const uint32_t sb = smem_to_u32(dsm);

    int by = blockIdx.y;
    if (causal) by = gridDim.y - 1 - by;
    const int bm = by * 128;
    const int bn = blockIdx.x * BN;
    if (causal == 1 && bn >= bm + 128) return;

    const int z = blockIdx.z;
    const int b = z / nh, h = z % nh;
    const size_t aoff = (size_t)b * sAb + (size_t)h * sAh;
    const size_t boff = (size_t)b * sBb + (size_t)h * sBh;
    const size_t coff = (size_t)b * sCb + (size_t)h * sCh;

    const int tid  = threadIdx.x;
    const int lane = tid & 31;
    const int wid  = tid >> 5;
    const int g = lane >> 2, t = lane & 3;
    const int m0 = (wid & 1) * 64;
    const int n0 = (wid >> 1) * WN;

    const bf16* Ah0 = Ahi + aoff + (size_t)bm * lda;
    const bf16* Al0 = Alo + aoff + (size_t)bm * lda;
    const bf16* Bh0 = Bhi + boff + (size_t)bn * ldb;
    const bf16* Bl0 = Blo + boff + (size_t)bn * ldb;

    float acc[4][NT][4];
#pragma unroll
    for (int i = 0; i < 4; i++)
#pragma unroll
        for (int j = 0; j < NT; j++)
#pragma unroll
            for (int r = 0; r < 4; r++) acc[i][j][r] = 0.f;

    int nchunks = K / 64;
    if (causal == 2) {
        int nc = (bm + 128) / 64;
        if (nc < nchunks) nchunks = nc;
    }

    const int arow = m0 + (lane & 15);
    const int akh  = lane >> 4;
    const int brow = n0 + ((lane >> 3) & 1) * 8 + (lane & 7);
    const int bkh  = lane >> 4;

#pragma unroll
    for (int s = 0; s < 2; ++s) {
        if (s < nchunks)
            stage_tiles<BN,256>(sb + (uint32_t)s * STG, Ah0 + s * 64, Al0 + s * 64,
                                Bh0 + s * 64, Bl0 + s * 64, lda, ldb, tid);
        CPC();
    }

    for (int c = 0; c < nchunks; ++c) {
        if (STAGES == 3) {
            CPW(1);
        } else {
            if (c + 1 < nchunks) CPW(1); else CPW(0);
        }
        __syncthreads();

        if (STAGES == 3) {
            int pf = c + 2;
            if (pf < nchunks)
                stage_tiles<BN,256>(sb + (uint32_t)(pf % 3) * STG,
                                    Ah0 + pf * 64, Al0 + pf * 64,
                                    Bh0 + pf * 64, Bl0 + pf * 64, lda, ldb, tid);
            CPC();
        }

        const uint32_t stg = sb + (uint32_t)(c % STAGES) * STG;
        const uint32_t aHi = stg, aLo = stg + ATB;
        const uint32_t bHi = stg + 2 * ATB, bLo = stg + 2 * ATB + BTB;

#pragma unroll
        for (int ks = 0; ks < 4; ++ks) {
            uint32_t ah[4][4], al[4][4], bfr[NT][2];
#pragma unroll
            for (int mt = 0; mt < 4; ++mt) {
                int row = arow + mt * 16;
                uint32_t off = (uint32_t)(row * 128 +
                    (((2 * ks + akh) ^ (row & 7)) << 4));
                LDSM4(ah[mt], aHi + off);
                LDSM4(al[mt], aLo + off);
            }
#pragma unroll
            for (int p = 0; p < NT / 2; ++p) {
                int row = brow + p * 16;
                uint32_t off = (uint32_t)(row * 128 +
                    (((2 * ks + bkh) ^ (row & 7)) << 4));
                uint32_t rh[4];
                LDSM4(rh, bHi + off);
                bfr[2 * p][0] = rh[0]; bfr[2 * p][1] = rh[2];
                bfr[2 * p + 1][0] = rh[1]; bfr[2 * p + 1][1] = rh[3];
            }
#pragma unroll
            for (int mt = 0; mt < 4; ++mt)
#pragma unroll
                for (int nt = 0; nt < NT; ++nt) {
                    mma16816(acc[mt][nt], ah[mt], bfr[nt]);
                    mma16816(acc[mt][nt], al[mt], bfr[nt]);
                }
#pragma unroll
            for (int p = 0; p < NT / 2; ++p) {
                int row = brow + p * 16;
                uint32_t off = (uint32_t)(row * 128 +
                    (((2 * ks + bkh) ^ (row & 7)) << 4));
                uint32_t rl[4];
                LDSM4(rl, bLo + off);
                bfr[2 * p][0] = rl[0]; bfr[2 * p][1] = rl[2];
                bfr[2 * p + 1][0] = rl[1]; bfr[2 * p + 1][1] = rl[3];
            }
#pragma unroll
            for (int mt = 0; mt < 4; ++mt)
#pragma unroll
                for (int nt = 0; nt < NT; ++nt)
                    mma16816(acc[mt][nt], ah[mt], bfr[nt]);
        }

        if (STAGES == 2) {
            __syncthreads();
            int pf = c + 2;
            if (pf < nchunks) {
                stage_tiles<BN,256>(sb + (uint32_t)(pf % 2) * STG,
                                    Ah0 + pf * 64, Al0 + pf * 64,
                                    Bh0 + pf * 64, Bl0 + pf * 64, lda, ldb, tid);
                CPC();
            }
        }
    }

#pragma unroll
    for (int mt = 0; mt < 4; ++mt) {
#pragma unroll
        for (int nt = 0; nt < NT; ++nt) {
            int row = bm + m0 + mt * 16 + g;
            int col = bn + n0 + nt * 8 + 2 * t;
            if (Cf) {
                *reinterpret_cast<float2*>(Cf + coff + (size_t)row * ldc + col) =
                    make_float2(acc[mt][nt][0], acc[mt][nt][1]);
                *reinterpret_cast<float2*>(Cf + coff + (size_t)(row + 8) * ldc + col) =
                    make_float2(acc[mt][nt][2], acc[mt][nt][3]);
            }
            if (Chi) {
                bf16 h0, l0, h1, l1;
                splitf(acc[mt][nt][0], h0, l0);
                splitf(acc[mt][nt][1], h1, l1);
                *reinterpret_cast<uint32_t*>(Chi + coff + (size_t)row * ldc + col) = pack2(h0, h1);
                *reinterpret_cast<uint32_t*>(Clo + coff + (size_t)row * ldc + col) = pack2(l0, l1);
                splitf(acc[mt][nt][2], h0, l0);
                splitf(acc[mt][nt][3], h1, l1);
                *reinterpret_cast<uint32_t*>(Chi + coff + (size_t)(row + 8) * ldc + col) = pack2(h0, h1);
                *reinterpret_cast<uint32_t*>(Clo + coff + (size_t)(row + 8) * ldc + col) = pack2(l0, l1);
            }
        }
    }
}

// ---------------- BN=256 GEMM, 512 threads (QK + Wo; proven R14) ----------------
__global__ __launch_bounds__(512) void gemm_bf16_512(
    const bf16* __restrict__ Ahi, const bf16* __restrict__ Alo,
    const bf16* __restrict__ Bhi, const bf16* __restrict__ Blo,
    float* __restrict__ Cf,
    int K, int lda, int ldb, int ldc,
    long long sAb, long long sAh, long long sBb, long long sBh,
    long long sCb, long long sCh, int nh, int causal)
{
    constexpr uint32_t ATB = 16384;
    constexpr uint32_t BTB = 256 * 128;
    constexpr uint32_t STG = 2 * ATB + 2 * BTB;

    extern __shared__ char dsm[];
    const uint32_t sb = smem_to_u32(dsm);

    int by = blockIdx.y;
    if (causal) by = gridDim.y - 1 - by;
    const int bm = by * 128;
    const int bn = blockIdx.x * 256;
    if (causal == 1 && bn >= bm + 128) return;

    const int z = blockIdx.z;
    const int b = z / nh, h = z % nh;
    const size_t aoff = (size_t)b * sAb + (size_t)h * sAh;
    const size_t boff = (size_t)b * sBb + (size_t)h * sBh;
    const size_t coff = (size_t)b * sCb + (size_t)h * sCh;

    const int tid  = threadIdx.x;
    const int lane = tid & 31;
    const int wid  = tid >> 5;
    const int g = lane >> 2, t = lane & 3;
    const int m0 = (wid & 3) * 32;
    const int n0 = (wid >> 2) * 64;

    const bf16* Ah0 = Ahi + aoff + (size_t)bm * lda;
    const bf16* Al0 = Alo + aoff + (size_t)bm * lda;
    const bf16* Bh0 = Bhi + boff + (size_t)bn * ldb;
    const bf16* Bl0 = Blo + boff + (size_t)bn * ldb;

    float acc[2][8][4];
#pragma unroll
    for (int i = 0; i < 2; i++)
#pragma unroll
        for (int j = 0; j < 8; j++)
#pragma unroll
            for (int r = 0; r < 4; r++) acc[i][j][r] = 0.f;

    int nchunks = K / 64;

    const int arow = m0 + (lane & 15);
    const int akh  = lane >> 4;
    const int brow = n0 + ((lane >> 3) & 1) * 8 + (lane & 7);
    const int bkh  = lane >> 4;

#pragma unroll
    for (int s = 0; s < 2; ++s) {
        if (s < nchunks)
            stage_tiles<256,512>(sb + (uint32_t)s * STG, Ah0 + s * 64, Al0 + s * 64,
                                 Bh0 + s * 64, Bl0 + s * 64, lda, ldb, tid);
        CPC();
    }

    for (int c = 0; c < nchunks; ++c) {
        if (c + 1 < nchunks) CPW(1); else CPW(0);
        __syncthreads();

        const uint32_t stg = sb + (uint32_t)(c & 1) * STG;
        const uint32_t aHi = stg, aLo = stg + ATB;
        const uint32_t bHi = stg + 2 * ATB, bLo = stg + 2 * ATB + BTB;

#pragma unroll
        for (int ks = 0; ks < 4; ++ks) {
            uint32_t af[2][4], bfr[8][2];

#pragma unroll
            for (int mt = 0; mt < 2; ++mt) {
                int row = arow + mt * 16;
                uint32_t off = (uint32_t)(row * 128 +
                    (((2 * ks + akh) ^ (row & 7)) << 4));
                LDSM4(af[mt], aHi + off);
            }
#pragma unroll
            for (int p = 0; p < 4; ++p) {
                int row = brow + p * 16;
                uint32_t off = (uint32_t)(row * 128 +
                    (((2 * ks + bkh) ^ (row & 7)) << 4));
                uint32_t rh[4];
                LDSM4(rh, bHi + off);
                bfr[2 * p][0] = rh[0]; bfr[2 * p][1] = rh[2];
                bfr[2 * p + 1][0] = rh[1]; bfr[2 * p + 1][1] = rh[3];
            }
#pragma unroll
            for (int mt = 0; mt < 2; ++mt)
#pragma unroll
                for (int nt = 0; nt < 8; ++nt)
                    mma16816(acc[mt][nt], af[mt], bfr[nt]);

#pragma unroll
            for (int mt = 0; mt < 2; ++mt) {
                int row = arow + mt * 16;
                uint32_t off = (uint32_t)(row * 128 +
                    (((2 * ks + akh) ^ (row & 7)) << 4));
                LDSM4(af[mt], aLo + off);
            }
#pragma unroll
            for (int mt = 0; mt < 2; ++mt)
#pragma unroll
                for (int nt = 0; nt < 8; ++nt)
                    mma16816(acc[mt][nt], af[mt], bfr[nt]);

#pragma unroll
            for (int mt = 0; mt < 2; ++mt) {
                int row = arow + mt * 16;
                uint32_t off = (uint32_t)(row * 128 +
                    (((2 * ks + akh) ^ (row & 7)) << 4));
                LDSM4(af[mt], aHi + off);
            }
#pragma unroll
            for (int p = 0; p < 4; ++p) {
                int row = brow + p * 16;
                uint32_t off = (uint32_t)(row * 128 +
                    (((2 * ks + bkh) ^ (row & 7)) << 4));
                uint32_t rl[4];
                LDSM4(rl, bLo + off);
                bfr[2 * p][0] = rl[0]; bfr[2 * p][1] = rl[2];
                bfr[2 * p + 1][0] = rl[1]; bfr[2 * p + 1][1] = rl[3];
            }
#pragma unroll
            for (int mt = 0; mt < 2; ++mt)
#pragma unroll
                for (int nt = 0; nt < 8; ++nt)
                    mma16816(acc[mt][nt], af[mt], bfr[nt]);
        }

        __syncthreads();
        int pf = c + 2;
        if (pf < nchunks) {
            stage_tiles<256,512>(sb + (uint32_t)(pf & 1) * STG,
                                 Ah0 + pf * 64, Al0 + pf * 64,
                                 Bh0 + pf * 64, Bl0 + pf * 64, lda, ldb, tid);
            CPC();
        }
    }

#pragma unroll
    for (int mt = 0; mt < 2; ++mt) {
#pragma unroll
        for (int nt = 0; nt < 8; ++nt) {
            int row = bm + m0 + mt * 16 + g;
            int col = bn + n0 + nt * 8 + 2 * t;
            *reinterpret_cast<float2*>(Cf + coff + (size_t)row * ldc + col) =
                make_float2(acc[mt][nt][0], acc[mt][nt][1]);
            *reinterpret_cast<float2*>(Cf + coff + (size_t)(row + 8) * ldc + col) =
                make_float2(acc[mt][nt][2], acc[mt][nt][3]);
        }
    }
}

// ---------------- elementwise bodies (proven) ----------------------------------
__device__ __forceinline__ void convert_body(
    const float* __restrict__ in, bf16* __restrict__ hi, bf16* __restrict__ lo,
    int idx, int n4)
{
    if (idx >= n4) return;
    float4 f = reinterpret_cast<const float4*>(in)[idx];
    bf16 h0,l0,h1,l1,h2,l2,h3,l3;
    splitf(f.x,h0,l0); splitf(f.y,h1,l1); splitf(f.z,h2,l2); splitf(f.w,h3,l3);
    reinterpret_cast<uint2*>(hi)[idx] = make_uint2(pack2(h0,h1), pack2(h2,h3));
    reinterpret_cast<uint2*>(lo)[idx] = make_uint2(pack2(l0,l1), pack2(l2,l3));
}

__device__ __forceinline__ void tr_body(
    float (*tile)[33],
    const float* __restrict__ in, bf16* __restrict__ ohi, bf16* __restrict__ olo,
    int R, int Cstride, int bx, int by, int tid)
{
    int c0 = bx * 32, r0 = by * 32;
    {
        int lr  = tid >> 3;
        int lc4 = (tid & 7) * 4;
        float4 f = *reinterpret_cast<const float4*>(
            in + (size_t)(r0 + lr) * Cstride + c0 + lc4);
        tile[lr][lc4 + 0] = f.x;
        tile[lr][lc4 + 1] = f.y;
        tile[lr][lc4 + 2] = f.z;
        tile[lr][lc4 + 3] = f.w;
    }
    __syncthreads();
    {
        int c  = tid >> 3;
        int rg = (tid & 7) * 4;
        bf16 h[4], l[4];
#pragma unroll
        for (int j = 0; j < 4; ++j)
            splitf(tile[rg + j][c], h[j], l[j]);
        size_t o = (size_t)(c0 + c) * R + r0 + rg;
        *reinterpret_cast<uint2*>(ohi + o) = make_uint2(pack2(h[0],h[1]), pack2(h[2],h[3]));
        *reinterpret_cast<uint2*>(olo + o) = make_uint2(pack2(l[0],l[1]), pack2(l[2],l[3]));
    }
}

__device__ __forceinline__ void rope_body(
    const float* __restrict__ x, const int* __restrict__ pos_ids,
    bf16* __restrict__ xhi, bf16* __restrict__ xlo,
    int nheads, int in_stride, int idx)
{
    const int half = HDD / 2;
    int total = BB * SS * nheads * half;
    if (idx >= total) return;
    int d = idx % half;
    int tt = idx / half;
    int h = tt % nheads;
    int s = (tt / nheads) % SS;
    int b = tt / (nheads * SS);

    float pos = (float)pos_ids[b * SS + s];
    float inv = exp2f(-(float)d * 0.103810253f);
    float ang = pos * inv;
    float c = cosf(ang), sn = sinf(ang);

    size_t ibase = (size_t)(b * SS + s) * in_stride + h * HDD;
    float x1 = x[ibase + d];
    float x2 = x[ibase + d + half];
    float r1 = x1 * c - x2 * sn;
    float r2 = x2 * c + x1 * sn;
    bf16 h1, l1, h2, l2;
    splitf(r1, h1, l1);
    splitf(r2, h2, l2);
    size_t obase = ((size_t)(b * SS + s) * nheads + h) * HDD;
    xhi[obase + d] = h1;        xlo[obase + d] = l1;
    xhi[obase + d + half] = h2; xlo[obase + d + half] = l2;
}

// ---------------- batched prep ---------------------------------------------------
__global__ __launch_bounds__(256) void prep_kernel(
    const float* __restrict__ hid, bf16* __restrict__ hhi, bf16* __restrict__ hlo,
    const float* __restrict__ Wq, const float* __restrict__ Wk,
    const float* __restrict__ Wv, const float* __restrict__ Wo,
    bf16* __restrict__ wTh, bf16* __restrict__ wTl,
    bf16* __restrict__ woh, bf16* __restrict__ wol)
{
    __shared__ float tile[32][33];
    int bid = blockIdx.x;
    int tid = threadIdx.x;

    if (bid < 8192) {
        convert_body(hid, hhi, hlo, bid * 256 + tid, (BB*SS*HIDD) / 4);
    } else if (bid < 12288) {
        int t = bid - 8192;
        tr_body(tile, Wq, wTh, wTl, HIDD, NHH*HDD, t % 64, t / 64, tid);
    } else if (bid < 12800) {
        int t = bid - 12288;
        tr_body(tile, Wk, wTh + (size_t)HIDD*HIDD, wTl + (size_t)HIDD*HIDD,
                HIDD, HDD, t % 8, t / 8, tid);
    } else if (bid < 13312) {
        int t = bid - 12800;
        tr_body(tile, Wv, wTh + (size_t)2304*HIDD, wTl + (size_t)2304*HIDD,
                HIDD, HDD, t % 8, t / 8, tid);
    } else {
        int t = bid - 13312;
        tr_body(tile, Wo, woh, wol, NHH*HDD, HIDD, t % 64, t / 64, tid);
    }
}

// ---------------- batched mid ------------------------------------------------------
__global__ __launch_bounds__(256) void mid_kernel(
    const float* __restrict__ qkvf, const int* __restrict__ pos,
    bf16* __restrict__ qhi, bf16* __restrict__ qlo,
    bf16* __restrict__ khi, bf16* __restrict__ klo,
    bf16* __restrict__ vth, bf16* __restrict__ vtl)
{
    __shared__ float tile[32][33];
    int bid = blockIdx.x;
    int tid = threadIdx.x;

    if (bid < 16384) {
        rope_body(qkvf, pos, qhi, qlo, NHH, 2560, bid * 256 + tid);
    } else if (bid < 18432) {
        rope_body(qkvf + 2048, pos, khi, klo, 1, 2560, (bid - 16384) * 256 + tid);
    } else {
        int t = bid - 18432;
        int bx = t % 8;
        int by = (t / 8) % 64;
        int bz = t / (8 * 64);
        tr_body(tile, qkvf + 2304 + (size_t)bz * SS * 2560,
                vth + (size_t)bz * HDD * SS, vtl + (size_t)bz * HDD * SS,
                SS, 2560, bx, by, tid);
    }
}

// ---------------- causal softmax -----------------------------------------------
__global__ __launch_bounds__(256) void softmax_kernel(
    const float* __restrict__ scores,
    float* __restrict__ out, bf16* __restrict__ ohi, bf16* __restrict__ olo,
    float scale)
{
    const int row = blockIdx.x;
    const int q  = row % SS;
    const float4* srow = reinterpret_cast<const float4*>(scores + (size_t)row * SS);
    const int k4max = (((q >> 7) + 1) << 7) >> 2;

    const int tid = threadIdx.x;
    float4 v[2];
    float mx = -INFINITY;
#pragma unroll
    for (int i = 0; i < 2; i++) {
        int k4 = tid + i * 256;
        if (k4 < k4max) {
            float4 s4 = srow[k4];
            int kb = 4 * k4;
            v[i].x = (kb + 0 <= q) ? s4.x * scale : -INFINITY;
            v[i].y = (kb + 1 <= q) ? s4.y * scale : -INFINITY;
            v[i].z = (kb + 2 <= q) ? s4.z * scale : -INFINITY;
            v[i].w = (kb + 3 <= q) ? s4.w * scale : -INFINITY;
            mx = fmaxf(mx, fmaxf(fmaxf(v[i].x, v[i].y), fmaxf(v[i].z, v[i].w)));
        } else {
            v[i] = make_float4(-INFINITY, -INFINITY, -INFINITY, -INFINITY);
        }
    }

    __shared__ float red[32];
#pragma unroll
    for (int o = 16; o > 0; o >>= 1)
        mx = fmaxf(mx, __shfl_xor_sync(0xFFFFFFFF, mx, o));
    if ((tid & 31) == 0) red[tid >> 5] = mx;
    __syncthreads();
    if (tid < 32) {
        float m = (tid < 8) ? red[tid] : -INFINITY;
#pragma unroll
        for (int o = 4; o > 0; o >>= 1)
            m = fmaxf(m, __shfl_xor_sync(0xFFFFFFFF, m, o));
        if (tid == 0) red[0] = m;
    }
    __syncthreads();
    mx = red[0];
    __syncthreads();

    float sum = 0.f;
#pragma unroll
    for (int i = 0; i < 2; i++) {
        v[i].x = __expf(v[i].x - mx);
        v[i].y = __expf(v[i].y - mx);
        v[i].z = __expf(v[i].z - mx);
        v[i].w = __expf(v[i].w - mx);
        sum += (v[i].x + v[i].y) + (v[i].z + v[i].w);
    }
#pragma unroll
    for (int o = 16; o > 0; o >>= 1)
        sum += __shfl_xor_sync(0xFFFFFFFF, sum, o);
    if ((tid & 31) == 0) red[tid >> 5] = sum;
    __syncthreads();
    if (tid < 32) {
        float s = (tid < 8) ? red[tid] : 0.f;
#pragma unroll
        for (int o = 4; o > 0; o >>= 1)
            s += __shfl_xor_sync(0xFFFFFFFF, s, o);
        if (tid == 0) red[0] = s;
    }
    __syncthreads();
    float inv = 1.0f / red[0];

    float4* orow = reinterpret_cast<float4*>(out + (size_t)row * SS);
    uint2* hrow = reinterpret_cast<uint2*>(ohi + (size_t)row * SS);
    uint2* lrow = reinterpret_cast<uint2*>(olo + (size_t)row * SS);
#pragma unroll
    for (int i = 0; i < 2; i++) {
        int k4 = tid + i * 256;
        if (k4 < k4max) {
            float4 p = make_float4(v[i].x * inv, v[i].y * inv,
                                   v[i].z * inv, v[i].w * inv);
            orow[k4] = p;
            bf16 h0,l0,h1,l1,h2,l2,h3,l3;
            splitf(p.x,h0,l0); splitf(p.y,h1,l1); splitf(p.z,h2,l2); splitf(p.w,h3,l3);
            hrow[k4] = make_uint2(pack2(h0,h1), pack2(h2,h3));
            lrow[k4] = make_uint2(pack2(l0,l1), pack2(l2,l3));
        } else {
            orow[k4] = make_float4(0.f, 0.f, 0.f, 0.f);
        }
    }
}

// ---------------- launch -------------------------------------------------------
extern "C" void kernel_launch(void* const* d_in, const int* in_sizes, int n_in,
                              void* d_out, int out_size)
{
    const float* hid  = (const float*)d_in[0];
    const int*   pos  = (const int*)d_in[2];
    const float* Wq   = (const float*)d_in[3];
    const float* Wk   = (const float*)d_in[4];
    const float* Wv   = (const float*)d_in[5];
    const float* Wo   = (const float*)d_in[6];
    float* out = (float*)d_out;

    float *qkvf, *scores;
    bf16 *hhi,*hlo,*wTh,*wTl,*woh,*wol;
    bf16 *qhi,*qlo,*khi,*klo,*vth,*vtl,*ahi,*alo,*chi,*clo;
    cudaGetSymbolAddress((void**)&qkvf, g_qkvf);
    cudaGetSymbolAddress((void**)&scores, g_scores);
    cudaGetSymbolAddress((void**)&hhi, g_hhi);
    cudaGetSymbolAddress((void**)&hlo, g_hlo);
    cudaGetSymbolAddress((void**)&wTh, g_wT_hi);
    cudaGetSymbolAddress((void**)&wTl, g_wT_lo);
    cudaGetSymbolAddress((void**)&woh, g_woT_hi);
    cudaGetSymbolAddress((void**)&wol, g_woT_lo);
    cudaGetSymbolAddress((void**)&qhi, g_qhi);
    cudaGetSymbolAddress((void**)&qlo, g_qlo);
    cudaGetSymbolAddress((void**)&khi, g_khi);
    cudaGetSymbolAddress((void**)&klo, g_klo);
    cudaGetSymbolAddress((void**)&vth, g_vthi);
    cudaGetSymbolAddress((void**)&vtl, g_vtlo);
    cudaGetSymbolAddress((void**)&ahi, g_ahi);
    cudaGetSymbolAddress((void**)&alo, g_alo);
    cudaGetSymbolAddress((void**)&chi, g_chi);
    cudaGetSymbolAddress((void**)&clo, g_clo);

    constexpr int SMEM_3S_128 = 3 * (2 * 16384 + 2 * 128 * 128);  // 196608
    constexpr int SMEM_512    = 2 * (2 * 16384 + 2 * 256 * 128);  // 196608
    cudaFuncSetAttribute((const void*)gemm_bf16<128,3>,
        cudaFuncAttributeMaxDynamicSharedMemorySize, SMEM_3S_128);
    cudaFuncSetAttribute((const void*)gemm_bf16_512,
        cudaFuncAttributeMaxDynamicSharedMemorySize, SMEM_512);

    const long long OUT_ATT = (long long)BB * SS * HIDD;
    const long long OUT_W   = (long long)BB * NHH * SS * SS;
    float* attnp = ((long long)out_size >= OUT_ATT + OUT_W) ? (out + OUT_ATT)
                                                            : scores;

    const int M = BB * SS;
    dim3 t256(256);
    dim3 t512(512);

    prep_kernel<<<17408, t256>>>(hid, hhi, hlo, Wq, Wk, Wv, Wo,
                                 wTh, wTl, woh, wol);

    // fused QKV projection (BN=128, 3-stage — best measured)
    gemm_bf16<128,3><<<dim3(2560/128, M/128, 1), t256, SMEM_3S_128>>>(
        hhi, hlo, wTh, wTl, qkvf, nullptr, nullptr,
        HIDD, HIDD, HIDD, 2560, 0,0,0,0,0,0, 1, 0);

    mid_kernel<<<19456, t256>>>(qkvf, pos, qhi, qlo, khi, klo, vth, vtl);

    // scores = Q @ K^T (512-thread, causal tile-skip — best measured)
    gemm_bf16_512<<<dim3(SS/256, SS/128, BB*NHH), t512, SMEM_512>>>(
        qhi, qlo, khi, klo, scores,
        HDD, NHH*HDD, HDD, SS,
        (long long)SS*NHH*HDD, HDD,
        (long long)SS*HDD, 0,
        (long long)NHH*SS*SS, (long long)SS*SS, NHH, 1);

    softmax_kernel<<<BB*NHH*SS, t256>>>(scores, attnp, ahi, alo,
                                        1.0f / sqrtf((float)HDD));

    // ctx = attn @ V (BN=128, 3-stage, bounded k — best measured)
    gemm_bf16<128,3><<<dim3(HDD/128, SS/128, BB*NHH), t256, SMEM_3S_128>>>(
        ahi, alo, vth, vtl, nullptr, chi, clo,
        SS, SS, SS, NHH*HDD,
        (long long)NHH*SS*SS, (long long)SS*SS,
        (long long)HDD*SS, 0,
        (long long)SS*NHH*HDD, HDD, NHH, 2);

    // out = ctx @ Wo (512-thread — best measured)
    gemm_bf16_512<<<dim3(HIDD/256, M/128, 1), t512, SMEM_512>>>(
        chi, clo, woh, wol, out,
        NHH*HDD, NHH*HDD, NHH*HDD, HIDD, 0,0,0,0,0,0, 1, 0);
}